// round 8
// baseline (speedup 1.0000x reference)
#include <cuda_runtime.h>
#include <cuda_bf16.h>
#include <cstdint>

#define NN 2048
#define KK 4095              // number of anti-diagonals = 2N-1
#define BIGF 1e10f
#define C_EXP 14.4269504088896340f   /* 1/(gamma*ln2), gamma=0.1 */
#define GLN2  0.0693147180559945f    /* gamma*ln2 = 1/C_EXP */
#define BIGC  (BIGF * C_EXP)
#define DSK_STRIDE ((size_t)NN)
#define DSK_MAT ((size_t)KK * (size_t)NN)   // 8,386,560 floats per matrix

// ---------------- device scratch (no allocations allowed) ----------------
__device__ float  g_dsk[3 * KK * NN];   // ~100.6 MB, diagonal-major D for xy/xx/yy
__device__ float  g_norms[2 * NN];      // row norms of a (first 2048) and b (next 2048)
__device__ double g_idm[2];             // idm_a, idm_b accumulators
__device__ float  g_sdtw[3];            // softdtw(xy), softdtw(xx), softdtw(yy)

// ---------------- fast math helpers ----------------
__device__ __forceinline__ float ex2f(float x) {
    float y; asm("ex2.approx.ftz.f32 %0, %1;" : "=f"(y) : "f"(x)); return y;
}
__device__ __forceinline__ float lg2f_(float x) {
    float y; asm("lg2.approx.f32 %0, %1;" : "=f"(y) : "f"(x)); return y;
}
__device__ __forceinline__ uint32_t smem_u32(const void* p) {
    uint32_t a;
    asm("{ .reg .u64 t; cvta.to.shared.u64 t, %1; cvt.u32.u64 %0, t; }" : "=r"(a) : "l"(p));
    return a;
}

// ---------------- row norms + accumulator init ----------------
__global__ void norms_kernel(const float* __restrict__ a, const float* __restrict__ b) {
    if (blockIdx.x == 0 && threadIdx.x == 0) { g_idm[0] = 0.0; g_idm[1] = 0.0; }
    int w    = blockIdx.x * (blockDim.x >> 5) + (threadIdx.x >> 5);
    int lane = threadIdx.x & 31;
    if (w >= 2 * NN) return;
    const float* src = (w < NN) ? (a + (size_t)w * 128) : (b + (size_t)(w - NN) * 128);
    float s = 0.0f;
#pragma unroll
    for (int q = 0; q < 4; q++) { float v = src[lane + 32 * q]; s = fmaf(v, v, s); }
#pragma unroll
    for (int off = 16; off; off >>= 1) s += __shfl_xor_sync(0xffffffffu, s, off);
    if (lane == 0) g_norms[w] = s;
}

// ---------------- pairwise sqdist GEMM: writes diagonal-major D, fuses idm ----------------
// stride-68 smem rows so the inner loop uses LDS.128 (float4).
__global__ void __launch_bounds__(256) pairdist_kernel(const float* __restrict__ a,
                                                       const float* __restrict__ b) {
    __shared__ float pool[2 * 64 * 68];   // 34,816 B
    float* xsT = pool;                    // [kk][ii], stride 68 (16B-aligned rows)
    float* ysT = pool + 64 * 68;

    const int z = blockIdx.z;             // 0: (a,b)  1: (a,a)  2: (b,b)
    const float* X  = (z == 2) ? b : a;
    const float* Y  = (z == 0) ? b : ((z == 1) ? a : b);
    const float* xn = g_norms + ((z == 2) ? NN : 0);
    const float* yn = g_norms + ((z == 1) ? 0 : NN);

    const int i0 = blockIdx.y * 64, j0 = blockIdx.x * 64;
    const int tid = threadIdx.x;
    const int tx = tid & 15, ty = tid >> 4;

    float acc[4][4];
#pragma unroll
    for (int r = 0; r < 4; r++)
#pragma unroll
        for (int c = 0; c < 4; c++) acc[r][c] = 0.0f;

    for (int kc = 0; kc < 128; kc += 64) {
        const int kk = tid & 63, ib = tid >> 6;
#pragma unroll
        for (int ii = ib; ii < 64; ii += 4) {
            xsT[kk * 68 + ii] = X[(size_t)(i0 + ii) * 128 + kc + kk];
            ysT[kk * 68 + ii] = Y[(size_t)(j0 + ii) * 128 + kc + kk];
        }
        __syncthreads();
#pragma unroll 4
        for (int k2 = 0; k2 < 64; ++k2) {
            float4 ra = *reinterpret_cast<const float4*>(&xsT[k2 * 68 + ty * 4]);
            float4 rb = *reinterpret_cast<const float4*>(&ysT[k2 * 68 + tx * 4]);
            const float rav[4] = {ra.x, ra.y, ra.z, ra.w};
            const float rbv[4] = {rb.x, rb.y, rb.z, rb.w};
#pragma unroll
            for (int r = 0; r < 4; r++)
#pragma unroll
                for (int c = 0; c < 4; c++) acc[r][c] = fmaf(rav[r], rbv[c], acc[r][c]);
        }
        __syncthreads();
    }

    float xnv[4], ynv[4];
#pragma unroll
    for (int r = 0; r < 4; r++) xnv[r] = xn[i0 + ty * 4 + r];
#pragma unroll
    for (int c = 0; c < 4; c++) ynv[c] = yn[j0 + tx * 4 + c];

    float* ds = pool;                     // reuse; 64 x 66 floats
    float lsum = 0.0f;
    const float inv_n = 1.0f / 2048.0f;
    const float thr   = 10.0f / 2048.0f;  // SIGMA / seq_len (exact in fp32)
#pragma unroll
    for (int r = 0; r < 4; r++) {
#pragma unroll
        for (int c = 0; c < 4; c++) {
            float d = fmaxf(xnv[r] + ynv[c] - 2.0f * acc[r][c], 0.0f);
            ds[(ty * 4 + r) * 66 + tx * 4 + c] = d;
            if (z) {
                int ig = i0 + ty * 4 + r, jg = j0 + tx * 4 + c;
                float gd   = (float)(ig - jg) * inv_n;
                float wgt  = fmaf(gd, gd, 1.0f);
                float diff = fabsf(gd) - thr;
                float prob = fmaxf(2.0f - d, 0.0f);
                lsum += (diff > 0.0f) ? (wgt * prob) : d;
            }
        }
    }
    if (z) {
#pragma unroll
        for (int off = 16; off; off >>= 1) lsum += __shfl_xor_sync(0xffffffffu, lsum, off);
        if ((tid & 31) == 0) atomicAdd(&g_idm[z - 1], (double)lsum);
    }
    __syncthreads();  // ds fully written before diag write-out

    float* dst = g_dsk + (size_t)z * DSK_MAT + (size_t)(i0 + j0) * DSK_STRIDE + i0;
    const int w = tid >> 5, lane = tid & 31;
    for (int d = w; d < 127; d += 8) {
        int lo = max(0, d - 63), hi = min(63, d);
        for (int e = lo + lane; e <= hi; e += 32) {
            dst[(size_t)d * DSK_STRIDE + e] = ds[e * 66 + (d - e)];
        }
    }
}

// ---------------- softDTW: branch-free wavefront (log2-scaled domain) ----------------
// 3 clusters x 8 CTAs x 256 threads, 1 element/thread. Zero C++ if-regions in the
// steady-state body: unconditional SEL-addressed cluster store for publish, raw-PTX
// monotone-tag poll, predicated prefetch. State u = r * C_EXP.
#define PF 8
__global__ void __launch_bounds__(256, 1) __cluster_dims__(8, 1, 1)
softdtw_kernel() {
    const int bz   = blockIdx.x;
    const int z    = bz >> 3;            // matrix id
    const int rank = bz & 7;             // segment within cluster (== cluster_ctarank)
    const float* __restrict__ dsk = g_dsk + (size_t)z * DSK_MAT;
    const int t = threadIdx.x;
    const int lane = t & 31, w = t >> 5;
    const int i = rank * 256 + t;        // global element index on each diagonal

    __shared__ unsigned long long inbox[4096];     // 32 KB: slot k -> left CTA boundary, tag>=k
    __shared__ unsigned long long ring[7][256];    // 14 KB: warp w -> w+1, 256-slot ring
    __shared__ unsigned long long sink[8];         // per-warp dummy publish target
    __shared__ unsigned long long polldummy;       // always-ready poll slot (tag=0xFFFFFFFF)
    __shared__ unsigned int prog[9];               // per-warp consumer progress

    for (int s = t; s < 4096; s += 256) inbox[s] = 0ULL;
    for (int s = t; s < 7 * 256; s += 256) ((unsigned long long*)ring)[s] = 0ULL;
    if (t < 9) prog[t] = 0u;
    if (t < 8) sink[t] = 0ULL;
    if (t == 0) {
        polldummy = (0xFFFFFFFFULL << 32) | (unsigned long long)__float_as_uint(BIGC);
        unsigned long long p0 = (1ULL << 32) | (unsigned long long)__float_as_uint(BIGC);
        for (int b = 0; b < 7; b++) ring[b][1] = p0;   // pre-publish diag-0 boundaries
    }
    __syncthreads();
    asm volatile("barrier.cluster.arrive.aligned;" ::: "memory");
    asm volatile("barrier.cluster.wait.aligned;" ::: "memory");

    const uint32_t inbox_a = smem_u32(inbox);
    const uint32_t ring_a  = smem_u32(ring);
    const uint32_t sink_a  = smem_u32(sink);
    const uint32_t poll_a  = smem_u32(&polldummy);
    const uint32_t prog_a  = smem_u32(prog);

    // cross-CTA pre-publish of diag-0 boundary into right neighbor's inbox[1]
    if (t == 255 && rank < 7) {
        uint32_t rem;
        asm("mapa.shared::cluster.u32 %0, %1, %2;" : "=r"(rem) : "r"(inbox_a), "r"(rank + 1));
        unsigned long long p0 = (1ULL << 32) | (unsigned long long)__float_as_uint(BIGC);
        asm volatile("st.shared::cluster.u64 [%0], %1;" :: "r"(rem + 8u), "l"(p0) : "memory");
    }

    // publish target (per-thread constants; selected once, no branches in loop)
    uint32_t loc, pmask; int trank = rank;
    if (lane == 31) {
        if (w < 7)        { loc = ring_a + (uint32_t)w * 2048u; pmask = 2047u; }
        else if (rank < 7){ loc = inbox_a; pmask = 32767u; trank = rank + 1; }
        else              { loc = sink_a + (uint32_t)w * 8u; pmask = 0u; }
    } else              { loc = sink_a + (uint32_t)w * 8u; pmask = 0u; }
    uint32_t pub_base;
    asm("mapa.shared::cluster.u32 %0, %1, %2;" : "=r"(pub_base) : "r"(loc), "r"(trank));

    // poll source
    uint32_t cbase, cmask;
    if (w == 0) {
        if (rank == 0) { cbase = poll_a;  cmask = 0u; }
        else           { cbase = inbox_a; cmask = 32767u; }
    } else             { cbase = ring_a + (uint32_t)(w - 1) * 2048u; cmask = 2047u; }

    const uint32_t myprog_a = prog_a + 4u * (uint32_t)w;
    const uint32_t rprog_a  = prog_a + 4u * (uint32_t)(w + 1);

    // state (scaled by C_EXP): r1 = u_{k-1}[i]; shp = u_{k-2}[i-1]; prev_in = boundary u_{k-2}[i-1]
    float r1 = (i == 0) ? dsk[0] * C_EXP : BIGC;
    float shp = BIGC, prev_in = BIGC;

    // D prefetch ring (pre-scaled), depth PF; rotation renamed away under unrolling
    float dd[PF];
#pragma unroll
    for (int q = 0; q < PF; q++) {
        int kn = 1 + q;
        bool ok = (kn <= KK - 1) && ((unsigned)(kn - i) <= (unsigned)(NN - 1));
        dd[q] = ok ? dsk[(size_t)kn * NN + i] * C_EXP : BIGC;
    }

    auto body = [&](int k) {
        // branchless prefetch of diag k+PF (clamped always-in-bounds load + SEL)
        const int kn  = k + PF;
        const int knc = (kn > KK - 1) ? (KK - 1) : kn;
        float v = __ldg(dsk + (size_t)knc * NN + i);
        bool ok = (kn <= KK - 1) && ((unsigned)(kn - i) <= (unsigned)(NN - 1));
        float dn = ok ? v * C_EXP : BIGC;

        // poll left boundary u_{k-1}: raw-PTX loop, monotone tag (tag >= k)
        uint32_t vlo, vhi;
        const uint32_t addr = cbase + (((uint32_t)k * 8u) & cmask);
        asm volatile(
            "{\n\t.reg .pred P;\n"
            "POLL%=:\n\t"
            "ld.volatile.shared.v2.u32 {%0,%1}, [%2];\n\t"
            "setp.lt.u32 P, %1, %3;\n\t"
            "@P bra POLL%=;\n\t}"
            : "=r"(vlo), "=r"(vhi) : "r"(addr), "r"((uint32_t)k) : "memory");
        float in1 = __uint_as_float(vlo);

        float sh  = __shfl_up_sync(0xffffffffu, r1, 1);
        float nb1 = (lane == 0) ? in1 : sh;        // u_{k-1}[i-1]
        float nb2 = (lane == 0) ? prev_in : shp;   // u_{k-2}[i-1]

        // scaled softmin: u = dC + m - lg2(sum ex2(m - u_i))
        float m  = fminf(fminf(nb2, nb1), r1);
        float e0 = ex2f(m - nb2);
        float e1 = ex2f(m - nb1);
        float e2 = ex2f(m - r1);
        float s  = (e0 + e1) + e2;
        float nv = (dd[0] + m) - lg2f_(s);

        shp = sh; prev_in = in1; r1 = nv;

        // unconditional publish (lane!=31 -> per-warp sink; lane31 -> ring or remote inbox)
        const uint32_t paddr = pub_base + (((uint32_t)(k + 1) * 8u) & pmask);
        asm volatile(
            "{\n\t.reg .b64 q;\n\t"
            "mov.b64 q, {%1, %2};\n\t"
            "st.shared::cluster.u64 [%0], q;\n\t}"
            :: "r"(paddr), "r"(__float_as_uint(r1)), "r"((uint32_t)(k + 1)) : "memory");

        // rotate prefetch ring
#pragma unroll
        for (int q = 0; q < PF - 1; q++) dd[q] = dd[q + 1];
        dd[PF - 1] = dn;
    };

    int k = 1;
#pragma unroll 1
    for (; k + (PF - 1) <= KK - 1; k += PF) {
        // progress (unconditional, same-address store) + rare backpressure check
        asm volatile("st.volatile.shared.u32 [%0], %1;" :: "r"(myprog_a), "r"((unsigned)k) : "memory");
        if (((unsigned)k & 31u) == 1u) {
            if (w < 7) {
                unsigned pr;
                do {
                    asm volatile("ld.volatile.shared.u32 %0, [%1];" : "=r"(pr) : "r"(rprog_a));
                } while ((unsigned)k - pr > 160u);
            }
        }
#pragma unroll
        for (int u = 0; u < PF; u++) body(k + u);
    }
#pragma unroll 1
    for (; k <= KK - 1; ++k) body(k);

    if (rank == 7 && t == 255) g_sdtw[z] = r1 * GLN2;   // rescale back

    asm volatile("barrier.cluster.arrive.aligned;" ::: "memory");
    asm volatile("barrier.cluster.wait.aligned;" ::: "memory");
}

// ---------------- combine ----------------
__global__ void finalize_kernel(float* out) {
    float pos = g_sdtw[0] - 0.5f * (g_sdtw[1] + g_sdtw[2]);
    float idm = (float)(g_idm[0] + g_idm[1]);
    out[0] = (pos + idm) / 2048.0f;    // ALPHA = 1, NUM_FRAMES = 2048
}

// ---------------- launch ----------------
extern "C" void kernel_launch(void* const* d_in, const int* in_sizes, int n_in,
                              void* d_out, int out_size) {
    const float* a = (const float*)d_in[0];   // a_emb [1,2048,128] fp32
    const float* b = (const float*)d_in[1];   // b_emb [1,2048,128] fp32
    (void)in_sizes; (void)n_in; (void)out_size;

    norms_kernel<<<512, 256>>>(a, b);
    dim3 g(32, 32, 3);
    pairdist_kernel<<<g, 256>>>(a, b);        // D in diagonal layout + fused idm
    softdtw_kernel<<<24, 256>>>();            // 3 clusters x 8 CTAs, branch-free wavefronts
    finalize_kernel<<<1, 1>>>((float*)d_out);
}

// round 10
// speedup vs baseline: 1.0375x; 1.0375x over previous
#include <cuda_runtime.h>
#include <cuda_bf16.h>
#include <cstdint>

#define NN 2048
#define KK 4095              // number of anti-diagonals = 2N-1
#define BIGF 1e10f
#define C_EXP 14.4269504088896340f   /* 1/(gamma*ln2), gamma=0.1 */
#define GLN2  0.0693147180559945f    /* gamma*ln2 = 1/C_EXP */
#define BIGC  (BIGF * C_EXP)
#define DSK_STRIDE ((size_t)NN)
#define DSK_MAT ((size_t)KK * (size_t)NN)   // 8,386,560 floats per matrix

// ---------------- device scratch (no allocations allowed) ----------------
__device__ float  g_dsk[3 * KK * NN];   // ~100.6 MB, diagonal-major D for xy/xx/yy
__device__ float  g_norms[2 * NN];      // row norms of a (first 2048) and b (next 2048)
__device__ double g_idm[2];             // idm_a, idm_b accumulators
__device__ float  g_sdtw[3];            // softdtw(xy), softdtw(xx), softdtw(yy)

// ---------------- fast math helpers ----------------
__device__ __forceinline__ float ex2f(float x) {
    float y; asm("ex2.approx.ftz.f32 %0, %1;" : "=f"(y) : "f"(x)); return y;
}
__device__ __forceinline__ float lg2f_(float x) {
    float y; asm("lg2.approx.f32 %0, %1;" : "=f"(y) : "f"(x)); return y;
}
__device__ __forceinline__ uint32_t smem_u32(const void* p) {
    uint32_t a;
    asm("{ .reg .u64 t; cvta.to.shared.u64 t, %1; cvt.u32.u64 %0, t; }" : "=r"(a) : "l"(p));
    return a;
}

// ---------------- row norms + accumulator init ----------------
__global__ void norms_kernel(const float* __restrict__ a, const float* __restrict__ b) {
    if (blockIdx.x == 0 && threadIdx.x == 0) { g_idm[0] = 0.0; g_idm[1] = 0.0; }
    int w    = blockIdx.x * (blockDim.x >> 5) + (threadIdx.x >> 5);
    int lane = threadIdx.x & 31;
    if (w >= 2 * NN) return;
    const float* src = (w < NN) ? (a + (size_t)w * 128) : (b + (size_t)(w - NN) * 128);
    float s = 0.0f;
#pragma unroll
    for (int q = 0; q < 4; q++) { float v = src[lane + 32 * q]; s = fmaf(v, v, s); }
#pragma unroll
    for (int off = 16; off; off >>= 1) s += __shfl_xor_sync(0xffffffffu, s, off);
    if (lane == 0) g_norms[w] = s;
}

// ---------------- pairwise sqdist GEMM: writes diagonal-major D, fuses idm ----------------
// stride-68 smem rows so the inner loop uses LDS.128 (float4).
__global__ void __launch_bounds__(256) pairdist_kernel(const float* __restrict__ a,
                                                       const float* __restrict__ b) {
    __shared__ float pool[2 * 64 * 68];   // 34,816 B
    float* xsT = pool;                    // [kk][ii], stride 68 (16B-aligned rows)
    float* ysT = pool + 64 * 68;

    const int z = blockIdx.z;             // 0: (a,b)  1: (a,a)  2: (b,b)
    const float* X  = (z == 2) ? b : a;
    const float* Y  = (z == 0) ? b : ((z == 1) ? a : b);
    const float* xn = g_norms + ((z == 2) ? NN : 0);
    const float* yn = g_norms + ((z == 1) ? 0 : NN);

    const int i0 = blockIdx.y * 64, j0 = blockIdx.x * 64;
    const int tid = threadIdx.x;
    const int tx = tid & 15, ty = tid >> 4;

    float acc[4][4];
#pragma unroll
    for (int r = 0; r < 4; r++)
#pragma unroll
        for (int c = 0; c < 4; c++) acc[r][c] = 0.0f;

    for (int kc = 0; kc < 128; kc += 64) {
        const int kk = tid & 63, ib = tid >> 6;
#pragma unroll
        for (int ii = ib; ii < 64; ii += 4) {
            xsT[kk * 68 + ii] = X[(size_t)(i0 + ii) * 128 + kc + kk];
            ysT[kk * 68 + ii] = Y[(size_t)(j0 + ii) * 128 + kc + kk];
        }
        __syncthreads();
#pragma unroll 4
        for (int k2 = 0; k2 < 64; ++k2) {
            float4 ra = *reinterpret_cast<const float4*>(&xsT[k2 * 68 + ty * 4]);
            float4 rb = *reinterpret_cast<const float4*>(&ysT[k2 * 68 + tx * 4]);
            const float rav[4] = {ra.x, ra.y, ra.z, ra.w};
            const float rbv[4] = {rb.x, rb.y, rb.z, rb.w};
#pragma unroll
            for (int r = 0; r < 4; r++)
#pragma unroll
                for (int c = 0; c < 4; c++) acc[r][c] = fmaf(rav[r], rbv[c], acc[r][c]);
        }
        __syncthreads();
    }

    float xnv[4], ynv[4];
#pragma unroll
    for (int r = 0; r < 4; r++) xnv[r] = xn[i0 + ty * 4 + r];
#pragma unroll
    for (int c = 0; c < 4; c++) ynv[c] = yn[j0 + tx * 4 + c];

    float* ds = pool;                     // reuse; 64 x 66 floats
    float lsum = 0.0f;
    const float inv_n = 1.0f / 2048.0f;
    const float thr   = 10.0f / 2048.0f;  // SIGMA / seq_len (exact in fp32)
#pragma unroll
    for (int r = 0; r < 4; r++) {
#pragma unroll
        for (int c = 0; c < 4; c++) {
            float d = fmaxf(xnv[r] + ynv[c] - 2.0f * acc[r][c], 0.0f);
            ds[(ty * 4 + r) * 66 + tx * 4 + c] = d;
            if (z) {
                int ig = i0 + ty * 4 + r, jg = j0 + tx * 4 + c;
                float gd   = (float)(ig - jg) * inv_n;
                float wgt  = fmaf(gd, gd, 1.0f);
                float diff = fabsf(gd) - thr;
                float prob = fmaxf(2.0f - d, 0.0f);
                lsum += (diff > 0.0f) ? (wgt * prob) : d;
            }
        }
    }
    if (z) {
#pragma unroll
        for (int off = 16; off; off >>= 1) lsum += __shfl_xor_sync(0xffffffffu, lsum, off);
        if ((tid & 31) == 0) atomicAdd(&g_idm[z - 1], (double)lsum);
    }
    __syncthreads();  // ds fully written before diag write-out

    float* dst = g_dsk + (size_t)z * DSK_MAT + (size_t)(i0 + j0) * DSK_STRIDE + i0;
    const int w = tid >> 5, lane = tid & 31;
    for (int d = w; d < 127; d += 8) {
        int lo = max(0, d - 63), hi = min(63, d);
        for (int e = lo + lane; e <= hi; e += 32) {
            dst[(size_t)d * DSK_STRIDE + e] = ds[e * 66 + (d - e)];
        }
    }
}

// ---------------- softDTW: wavefront with predicated publish (no BSSY) ----------------
// 3 clusters x 8 CTAs x 256 threads, 1 element/thread. log2-scaled state u = r * C_EXP.
// Publish = @p st (single predicated instruction, local STS for ring, cluster store for CTA edge).
// Poll = raw-PTX monotone-tag loop on a warp-uniform slot (dummy always-ready slot for rank0/w0).
#define PF 8
__global__ void __launch_bounds__(256, 1) __cluster_dims__(8, 1, 1)
softdtw_kernel() {
    const int bz   = blockIdx.x;
    const int z    = bz >> 3;            // matrix id
    const int rank = bz & 7;             // segment within cluster
    const float* __restrict__ dsk = g_dsk + (size_t)z * DSK_MAT;
    const int t = threadIdx.x;
    const int lane = t & 31, w = t >> 5;
    const int i = rank * 256 + t;        // global element index on each diagonal

    __shared__ unsigned long long inbox[4096];     // 32 KB: slot k -> left CTA boundary, tag>=k
    __shared__ unsigned long long ring[7][256];    // 14 KB: warp w -> w+1, 256-slot ring
    __shared__ unsigned long long polldummy;       // always-ready poll slot (tag=0xFFFFFFFF)
    __shared__ unsigned int prog[8];               // per-warp consumer progress

    for (int s = t; s < 4096; s += 256) inbox[s] = 0ULL;
    for (int s = t; s < 7 * 256; s += 256) ((unsigned long long*)ring)[s] = 0ULL;
    if (t < 8) prog[t] = 0u;
    if (t == 0) {
        polldummy = (0xFFFFFFFFULL << 32) | (unsigned long long)__float_as_uint(BIGC);
        unsigned long long p0 = (1ULL << 32) | (unsigned long long)__float_as_uint(BIGC);
        for (int b = 0; b < 7; b++) ring[b][1] = p0;   // pre-publish diag-0 boundaries
    }
    __syncthreads();
    asm volatile("barrier.cluster.arrive.aligned;" ::: "memory");
    asm volatile("barrier.cluster.wait.aligned;" ::: "memory");

    const uint32_t inbox_a = smem_u32(inbox);
    const uint32_t ring_a  = smem_u32(ring);
    const uint32_t poll_a  = smem_u32(&polldummy);
    const uint32_t prog_a  = smem_u32(prog);

    // remote inbox of right neighbor (valid when rank<7; self otherwise, never stored)
    uint32_t rem_inbox;
    {
        int trank = (rank < 7) ? rank + 1 : rank;
        asm("mapa.shared::cluster.u32 %0, %1, %2;" : "=r"(rem_inbox) : "r"(inbox_a), "r"(trank));
    }
    // cross-CTA pre-publish of diag-0 boundary into right neighbor's inbox[1]
    if (t == 255 && rank < 7) {
        unsigned long long p0 = (1ULL << 32) | (unsigned long long)__float_as_uint(BIGC);
        asm volatile("st.shared::cluster.u64 [%0], %1;" :: "r"(rem_inbox + 8u), "l"(p0) : "memory");
    }

    // publish predicates (loop-invariant 0/1 ints) + uniform bases
    const uint32_t pring = (lane == 31 && w < 7) ? 1u : 0u;
    const uint32_t pdsm  = (lane == 31 && w == 7 && rank < 7) ? 1u : 0u;
    const uint32_t prod_base = ring_a + (uint32_t)((w < 7 ? w : 6) * 2048);

    // poll source (warp-uniform)
    uint32_t cbase, cmask;
    if (w == 0) {
        if (rank == 0) { cbase = poll_a;  cmask = 0u; }
        else           { cbase = inbox_a; cmask = 32767u; }
    } else             { cbase = ring_a + (uint32_t)(w - 1) * 2048u; cmask = 2047u; }

    const uint32_t myprog_a = prog_a + 4u * (uint32_t)w;
    const uint32_t rprog_a  = prog_a + 4u * (uint32_t)((w < 7 ? w : 6) + 1);

    // state (scaled by C_EXP): r1 = u_{k-1}[i]; shp = u_{k-2}[i-1]; prev_in = boundary u_{k-2}[i-1]
    float r1 = (i == 0) ? dsk[0] * C_EXP : BIGC;
    float shp = BIGC, prev_in = BIGC;

    // D prefetch ring (pre-scaled), depth PF; rotation renamed away under unrolling
    float dd[PF];
#pragma unroll
    for (int q = 0; q < PF; q++) {
        int kn = 1 + q;
        bool ok = (kn <= KK - 1) && ((unsigned)(kn - i) <= (unsigned)(NN - 1));
        dd[q] = ok ? dsk[(size_t)kn * NN + i] * C_EXP : BIGC;
    }

    auto body = [&](int k) {
        // branchless prefetch of diag k+PF (clamped always-in-bounds load + SEL)
        const int kn  = k + PF;
        const int knc = (kn > KK - 1) ? (KK - 1) : kn;
        float v = __ldg(dsk + (size_t)knc * NN + i);
        bool ok = (kn <= KK - 1) && ((unsigned)(kn - i) <= (unsigned)(NN - 1));
        float dn = ok ? v * C_EXP : BIGC;

        // poll left boundary u_{k-1}: raw-PTX loop, monotone tag (tag >= k)
        uint32_t vlo, vhi;
        const uint32_t addr = cbase + (((uint32_t)k * 8u) & cmask);
        asm volatile(
            "{\n\t.reg .pred P;\n"
            "POLL%=:\n\t"
            "ld.volatile.shared.v2.u32 {%0,%1}, [%2];\n\t"
            "setp.lt.u32 P, %1, %3;\n\t"
            "@P bra POLL%=;\n\t}"
            : "=r"(vlo), "=r"(vhi) : "r"(addr), "r"((uint32_t)k) : "memory");
        float in1 = __uint_as_float(vlo);

        float sh  = __shfl_up_sync(0xffffffffu, r1, 1);
        float nb1 = (lane == 0) ? in1 : sh;        // u_{k-1}[i-1]
        float nb2 = (lane == 0) ? prev_in : shp;   // u_{k-2}[i-1]

        // scaled softmin: u = dC + m - lg2(sum ex2(m - u_i))
        float m  = fminf(fminf(nb2, nb1), r1);
        float e0 = ex2f(m - nb2);
        float e1 = ex2f(m - nb1);
        float e2 = ex2f(m - r1);
        float s  = (e0 + e1) + e2;
        float nv = (dd[0] + m) - lg2f_(s);

        shp = sh; prev_in = in1; r1 = nv;

        // publish r_k boundary (tag k+1): two single predicated stores, no branches
        const uint32_t rlo = __float_as_uint(r1);
        const uint32_t tag = (uint32_t)(k + 1);
        const uint32_t ra  = prod_base + ((tag * 8u) & 2047u);
        asm volatile(
            "{\n\t.reg .pred p;\n\t.reg .b64 q;\n\t"
            "setp.ne.u32 p, %0, 0;\n\t"
            "mov.b64 q, {%2, %3};\n\t"
            "@p st.volatile.shared.u64 [%1], q;\n\t}"
            :: "r"(pring), "r"(ra), "r"(rlo), "r"(tag) : "memory");
        asm volatile(
            "{\n\t.reg .pred p;\n\t.reg .b64 q;\n\t"
            "setp.ne.u32 p, %0, 0;\n\t"
            "mov.b64 q, {%2, %3};\n\t"
            "@p st.shared::cluster.u64 [%1], q;\n\t}"
            :: "r"(pdsm), "r"(rem_inbox + tag * 8u), "r"(rlo), "r"(tag) : "memory");

        // rotate prefetch ring (renamed away under unrolling)
#pragma unroll
        for (int q = 0; q < PF - 1; q++) dd[q] = dd[q + 1];
        dd[PF - 1] = dn;
    };

    int k = 1;
#pragma unroll 1
    for (; k + (PF - 1) <= KK - 1; k += PF) {
        // progress publish + rare ring backpressure (window 160+32+8 < 256 slots)
        asm volatile("st.volatile.shared.u32 [%0], %1;" :: "r"(myprog_a), "r"((unsigned)k) : "memory");
        if (((unsigned)k & 31u) == 1u) {
            if (w < 7) {
                unsigned pr;
                do {
                    asm volatile("ld.volatile.shared.u32 %0, [%1];" : "=r"(pr) : "r"(rprog_a));
                } while ((unsigned)k - pr > 160u);
            }
        }
#pragma unroll
        for (int u = 0; u < PF; u++) body(k + u);
    }
#pragma unroll 1
    for (; k <= KK - 1; ++k) body(k);

    if (rank == 7 && t == 255) g_sdtw[z] = r1 * GLN2;   // rescale back

    asm volatile("barrier.cluster.arrive.aligned;" ::: "memory");
    asm volatile("barrier.cluster.wait.aligned;" ::: "memory");
}

// ---------------- profiling-alignment dummy (shifts ncu's skip-5 capture onto softdtw) ----------------
__global__ void dummy_kernel() {}

// ---------------- combine ----------------
__global__ void finalize_kernel(float* out) {
    float pos = g_sdtw[0] - 0.5f * (g_sdtw[1] + g_sdtw[2]);
    float idm = (float)(g_idm[0] + g_idm[1]);
    out[0] = (pos + idm) / 2048.0f;    // ALPHA = 1, NUM_FRAMES = 2048
}

// ---------------- launch ----------------
extern "C" void kernel_launch(void* const* d_in, const int* in_sizes, int n_in,
                              void* d_out, int out_size) {
    const float* a = (const float*)d_in[0];   // a_emb [1,2048,128] fp32
    const float* b = (const float*)d_in[1];   // b_emb [1,2048,128] fp32
    (void)in_sizes; (void)n_in; (void)out_size;

    norms_kernel<<<512, 256>>>(a, b);
    dim3 g(32, 32, 3);
    pairdist_kernel<<<g, 256>>>(a, b);        // D in diagonal layout + fused idm
    dummy_kernel<<<1, 32>>>();                // alignment shim: makes skip-5 capture hit softdtw
    softdtw_kernel<<<24, 256>>>();            // 3 clusters x 8 CTAs, predicated-publish wavefronts
    finalize_kernel<<<1, 1>>>((float*)d_out);
}